// round 4
// baseline (speedup 1.0000x reference)
#include <cuda_runtime.h>
#include <cstdint>

// Scatter-add edge_features [B, M, F] into out [B, N, N, F] at (b, i, j),
// restructured as a per-(b,i)-row GATHER so the output is written exactly
// once (fuses the zero-fill with the accumulation; no global atomics).
// Dataset: B=32, M=4096, F=64, N=128. pair_indices may be int32 or int64.

static constexpr int N_ATOMS = 128;
static constexpr int F_DIM   = 64;
static constexpr int MAX_EDGES = 1 << 17;  // B*M = 131072

// Packed keys: (i << 8) | j per edge; 0xFFFF = out-of-range sentinel.
__device__ unsigned short g_keys[MAX_EDGES];

// ---------------------------------------------------------------------------
// K0: pack indices into u16 keys. Each block runs its own dtype probe on the
// first 32 pairs (int64 layout => every odd 32-bit word is a zero high half;
// int32 => odd words are random j in [0,128), P(all zero) ~ 128^-32).
// ---------------------------------------------------------------------------
__global__ void pack_kernel(const void* __restrict__ pair_raw, int n_edges) {
    __shared__ int s_is64;
    const int* words = (const int*)pair_raw;
    if (threadIdx.x < 32) {
        int w = words[threadIdx.x * 2 + 1];
        unsigned ball = __ballot_sync(0xffffffffu, w == 0);
        if (threadIdx.x == 0) s_is64 = (ball == 0xffffffffu) ? 1 : 0;
    }
    __syncthreads();
    const int is64 = s_is64;

    int e = blockIdx.x * blockDim.x + threadIdx.x;
    if (e >= n_edges) return;

    unsigned i, j;
    if (is64) {
        longlong2 v = ((const longlong2*)pair_raw)[e];
        i = (unsigned)v.x; j = (unsigned)v.y;
    } else {
        int2 v = ((const int2*)pair_raw)[e];
        i = (unsigned)v.x; j = (unsigned)v.y;
    }
    g_keys[e] = (i < N_ATOMS && j < N_ATOMS)
                    ? (unsigned short)((i << 8) | j)
                    : (unsigned short)0xFFFF;
}

// ---------------------------------------------------------------------------
// K1: one block per (b, i) output row [N, F] = 32 KB.
// Zero SMEM row -> scan batch keys, accumulate matching edges via shared
// atomics -> single coalesced store. Output written exactly once.
// ---------------------------------------------------------------------------
__global__ void __launch_bounds__(256)
row_kernel(const float4* __restrict__ edge_feat4,  // [B*M*16] float4
           float* __restrict__ out,                // [B*N*N*F]
           int M)                                  // edges per batch
{
    __shared__ float srow[N_ATOMS * F_DIM];  // 32 KB

    const int b = blockIdx.x >> 7;       // / N_ATOMS
    const int i = blockIdx.x & 127;      // % N_ATOMS
    constexpr int ROW4 = N_ATOMS * F_DIM / 4;  // 2048 float4

    // zero the row tile
    float4* srow4 = (float4*)srow;
    for (int t = threadIdx.x; t < ROW4; t += blockDim.x)
        srow4[t] = make_float4(0.f, 0.f, 0.f, 0.f);
    __syncthreads();

    // scan this batch's keys (coalesced: thread t reads e = t, t+256, ...)
    const unsigned short* keys = g_keys + b * M;
    const unsigned short want = (unsigned short)(i << 8);
    for (int e = threadIdx.x; e < M; e += blockDim.x) {
        unsigned short key = keys[e];
        if ((unsigned short)(key & 0xFF00) == want) {
            int j = key & 0xFF;
            const float4* src = edge_feat4 + ((long long)(b * M + e) << 4);
            float* dst = srow + j * F_DIM;
            #pragma unroll
            for (int c = 0; c < 16; c++) {
                float4 v = src[c];
                atomicAdd(dst + c * 4 + 0, v.x);
                atomicAdd(dst + c * 4 + 1, v.y);
                atomicAdd(dst + c * 4 + 2, v.z);
                atomicAdd(dst + c * 4 + 3, v.w);
            }
        }
    }
    __syncthreads();

    // single coalesced store of the finished row
    float4* orow = (float4*)(out + (long long)blockIdx.x * (N_ATOMS * F_DIM));
    for (int t = threadIdx.x; t < ROW4; t += blockDim.x)
        orow[t] = srow4[t];
}

// ---------------------------------------------------------------------------
// Launch
// ---------------------------------------------------------------------------
extern "C" void kernel_launch(void* const* d_in, const int* in_sizes, int n_in,
                              void* d_out, int out_size)
{
    const float* edge_features = (const float*)d_in[0];  // [B, M, F]
    const void*  pair_indices  = d_in[1];                // [B, M, 2]

    int n_edges = in_sizes[1] / 2;                       // B*M (131072 if i32)
    // If indices are int64 the size-derived edge count halves; recompute from
    // the feature buffer instead (always F floats per edge).
    int n_edges_feat = in_sizes[0] / F_DIM;
    n_edges = n_edges_feat;                              // robust either way

    int B = out_size / (N_ATOMS * N_ATOMS * F_DIM);      // 32
    int M = n_edges / B;                                 // 4096

    float* out = (float*)d_out;

    // K0: pack + probe
    {
        int threads = 256;
        int blocks  = (n_edges + threads - 1) / threads;
        pack_kernel<<<blocks, threads>>>(pair_indices, n_edges);
    }

    // K1: fused zero + gather + store, one block per (b, i) row
    {
        int blocks = B * N_ATOMS;                        // 4096
        row_kernel<<<blocks, 256>>>((const float4*)edge_features, out, M);
    }
}

// round 5
// speedup vs baseline: 3.5517x; 3.5517x over previous
#include <cuda_runtime.h>
#include <cstdint>

// Scatter-add edge_features [B, M, F] into out [B, N, N, F] at (b, i, j),
// restructured as a per-(b,i)-row gather: output written exactly once,
// no global atomics, and (this round) no shared atomics in the hot path.
// Dataset: B=32, M=4096, F=64, N=128. pair_indices may be int32 or int64.

static constexpr int N_ATOMS = 128;
static constexpr int F_DIM   = 64;
static constexpr int MAX_EDGES = 1 << 17;   // B*M = 131072
static constexpr int LIST_CAP  = 192;       // Poisson(32); P(>192) ~ 0

// Packed keys: (i << 8) | j per edge; 0xFFFF = out-of-range sentinel.
__device__ unsigned short g_keys[MAX_EDGES];

// ---------------------------------------------------------------------------
// K0: pack indices into u16 keys. Per-block dtype probe: int64 layout means
// every odd 32-bit word is the zero high half of a value < 128; int32 means
// odd words are random j in [0,128) (P(32 zeros) ~ 128^-32).
// ---------------------------------------------------------------------------
__global__ void pack_kernel(const void* __restrict__ pair_raw, int n_edges) {
    __shared__ int s_is64;
    const int* words = (const int*)pair_raw;
    if (threadIdx.x < 32) {
        int w = words[threadIdx.x * 2 + 1];
        unsigned ball = __ballot_sync(0xffffffffu, w == 0);
        if (threadIdx.x == 0) s_is64 = (ball == 0xffffffffu) ? 1 : 0;
    }
    __syncthreads();
    const int is64 = s_is64;

    int e = blockIdx.x * blockDim.x + threadIdx.x;
    if (e >= n_edges) return;

    unsigned i, j;
    if (is64) {
        longlong2 v = ((const longlong2*)pair_raw)[e];
        i = (unsigned)v.x; j = (unsigned)v.y;
    } else {
        int2 v = ((const int2*)pair_raw)[e];
        i = (unsigned)v.x; j = (unsigned)v.y;
    }
    g_keys[e] = (i < N_ATOMS && j < N_ATOMS)
                    ? (unsigned short)((i << 8) | j)
                    : (unsigned short)0xFFFF;
}

// ---------------------------------------------------------------------------
// K1: one block per (b, i) output row [N, F] = 32 KB.
//   Phase 1: vectorized key scan -> compact match list (e<<8)|j in SMEM.
//   Phase 2: warp w owns j%8==w rows; serial per-warp walk of the list,
//            coalesced float2 edge loads, race-free SMEM accumulation.
//   Phase 3: one coalesced 32 KB store.
// ---------------------------------------------------------------------------
__global__ void __launch_bounds__(256)
row_kernel(const float2* __restrict__ edge_feat2,  // [B*M*32] float2
           float* __restrict__ out,                // [B*N*N*F]
           int M)                                  // edges per batch
{
    __shared__ float srow[N_ATOMS * F_DIM];        // 32 KB
    __shared__ unsigned s_list[LIST_CAP];          // (e<<8)|j
    __shared__ int s_cnt;

    const int b = blockIdx.x >> 7;
    const int i = blockIdx.x & 127;
    constexpr int ROW4 = N_ATOMS * F_DIM / 4;      // 2048 float4

    if (threadIdx.x == 0) s_cnt = 0;
    // zero the row tile (concurrent with counter init; one barrier below)
    float4* srow4 = (float4*)srow;
    for (int t = threadIdx.x; t < ROW4; t += blockDim.x)
        srow4[t] = make_float4(0.f, 0.f, 0.f, 0.f);
    __syncthreads();

    // Phase 1: scan this batch's keys, 8 keys (uint4) per load, coalesced.
    {
        const uint4* keys4 = (const uint4*)(g_keys + b * M);
        const int n4 = M >> 3;                     // 512
        for (int t = threadIdx.x; t < n4; t += blockDim.x) {
            uint4 kv = keys4[t];
            unsigned ww[4] = {kv.x, kv.y, kv.z, kv.w};
            #pragma unroll
            for (int w = 0; w < 4; w++) {
                unsigned k0 = ww[w] & 0xFFFFu;
                unsigned k1 = ww[w] >> 16;
                int e0 = t * 8 + w * 2;
                if ((int)(k0 >> 8) == i) {
                    int pos = atomicAdd(&s_cnt, 1);
                    if (pos < LIST_CAP)
                        s_list[pos] = ((unsigned)e0 << 8) | (k0 & 0xFFu);
                }
                if ((int)(k1 >> 8) == i) {
                    int pos = atomicAdd(&s_cnt, 1);
                    if (pos < LIST_CAP)
                        s_list[pos] = ((unsigned)(e0 + 1) << 8) | (k1 & 0xFFu);
                }
            }
        }
    }
    __syncthreads();

    // Phase 2: warp-ownership accumulation, no atomics.
    {
        const int warp = threadIdx.x >> 5;
        const int lane = threadIdx.x & 31;
        const int cnt  = min(s_cnt, LIST_CAP);
        const long long base_e = (long long)b * M;
        for (int idx = 0; idx < cnt; idx++) {
            unsigned ent = s_list[idx];
            int j = (int)(ent & 0xFFu);
            if ((j & 7) != warp) continue;          // warp-uniform test
            int e = (int)(ent >> 8);
            // coalesced 256 B read: lane -> 8 bytes
            float2 v = edge_feat2[(base_e + e) * 32 + lane];
            float* dst = srow + j * F_DIM + lane * 2;
            dst[0] += v.x;
            dst[1] += v.y;
        }
    }
    __syncthreads();

    // Phase 3: single coalesced store of the finished row.
    float4* orow = (float4*)(out + (long long)blockIdx.x * (N_ATOMS * F_DIM));
    for (int t = threadIdx.x; t < ROW4; t += blockDim.x)
        orow[t] = srow4[t];
}

// ---------------------------------------------------------------------------
// Launch
// ---------------------------------------------------------------------------
extern "C" void kernel_launch(void* const* d_in, const int* in_sizes, int n_in,
                              void* d_out, int out_size)
{
    const float* edge_features = (const float*)d_in[0];  // [B, M, F]
    const void*  pair_indices  = d_in[1];                // [B, M, 2]

    int n_edges = in_sizes[0] / F_DIM;                   // robust to idx dtype
    int B = out_size / (N_ATOMS * N_ATOMS * F_DIM);      // 32
    int M = n_edges / B;                                 // 4096

    float* out = (float*)d_out;

    // K0: pack + probe
    {
        int threads = 256;
        int blocks  = (n_edges + threads - 1) / threads;
        pack_kernel<<<blocks, threads>>>(pair_indices, n_edges);
    }

    // K1: fused zero + gather + store, one block per (b, i) row
    {
        int blocks = B * N_ATOMS;                        // 4096
        row_kernel<<<blocks, 256>>>((const float2*)edge_features, out, M);
    }
}

// round 6
// speedup vs baseline: 4.1097x; 1.1571x over previous
#include <cuda_runtime.h>
#include <cstdint>

// Scatter-add edge_features [B, M, F] into out [B, N, N, F] at (b, i, j).
// Strategy: chunked zero-fill + atomic scatter, with the scatter of chunk k
// overlapped (2nd stream, event-gated) against the zero-fill of chunks k+1...
// so atomic RMW hits freshly-zeroed L2-resident lines and each output line
// goes to DRAM exactly once. Dataset: B=32, M=4096, F=64, N=128.

static constexpr int N_ATOMS = 128;
static constexpr int F_DIM   = 64;
static constexpr int MAX_EDGES = 1 << 17;     // B*M
static constexpr int BATCHES_PER_CHUNK = 4;   // 16.75 MB output per chunk
static constexpr int MAX_CHUNKS = 32;

// Packed keys: (i << 8) | j per edge; 0xFFFF = out-of-range sentinel.
__device__ unsigned short g_keys[MAX_EDGES];

// ---------------------------------------------------------------------------
// K0: pack indices into u16 keys; per-block dtype probe (int64 layout => odd
// 32-bit words are zero high halves of values < 128; int32 => random j).
// ---------------------------------------------------------------------------
__global__ void pack_kernel(const void* __restrict__ pair_raw, int n_edges) {
    __shared__ int s_is64;
    const int* words = (const int*)pair_raw;
    if (threadIdx.x < 32) {
        int w = words[threadIdx.x * 2 + 1];
        unsigned ball = __ballot_sync(0xffffffffu, w == 0);
        if (threadIdx.x == 0) s_is64 = (ball == 0xffffffffu) ? 1 : 0;
    }
    __syncthreads();
    const int is64 = s_is64;

    int e = blockIdx.x * blockDim.x + threadIdx.x;
    if (e >= n_edges) return;

    unsigned i, j;
    if (is64) {
        longlong2 v = ((const longlong2*)pair_raw)[e];
        i = (unsigned)v.x; j = (unsigned)v.y;
    } else {
        int2 v = ((const int2*)pair_raw)[e];
        i = (unsigned)v.x; j = (unsigned)v.y;
    }
    g_keys[e] = (i < N_ATOMS && j < N_ATOMS)
                    ? (unsigned short)((i << 8) | j)
                    : (unsigned short)0xFFFF;
}

// ---------------------------------------------------------------------------
// Zero-fill one output chunk.
// ---------------------------------------------------------------------------
__global__ void zero_kernel(float4* __restrict__ out, int n4) {
    int idx    = blockIdx.x * blockDim.x + threadIdx.x;
    int stride = gridDim.x * blockDim.x;
    float4 z = make_float4(0.f, 0.f, 0.f, 0.f);
    for (; idx < n4; idx += stride) out[idx] = z;
}

// ---------------------------------------------------------------------------
// Scatter one chunk's edges: 16 threads/edge, red.global.add.v4.f32 into the
// freshly zeroed (L2-resident) chunk.
// ---------------------------------------------------------------------------
__global__ void scatter_kernel(const float4* __restrict__ edge_feat4,  // global base
                               float* __restrict__ out,                // global base
                               int b0,                                 // first batch
                               int n_chunk_edges,                      // batches*M
                               int M)
{
    int tid = blockIdx.x * blockDim.x + threadIdx.x;
    if (tid >= n_chunk_edges * (F_DIM / 4)) return;

    int le    = tid >> 4;            // local edge in chunk
    int chunk = tid & 15;
    int ge    = b0 * M + le;         // global edge
    int b     = b0 + le / M;

    unsigned short key = g_keys[ge];
    if (key == 0xFFFFu) return;
    unsigned i = key >> 8;
    unsigned j = key & 0xFFu;

    float4 v = edge_feat4[((long long)ge << 4) + chunk];

    unsigned dst = ((((unsigned)b * N_ATOMS + i) * N_ATOMS + j) * F_DIM)
                   + (unsigned)chunk * 4;
    float* dptr = out + dst;

    asm volatile("red.global.add.v4.f32 [%0], {%1, %2, %3, %4};"
                 :
                 : "l"(dptr), "f"(v.x), "f"(v.y), "f"(v.z), "f"(v.w)
                 : "memory");
}

// ---------------------------------------------------------------------------
// Launch: pack -> per-chunk {zero on default stream, scatter on 2nd stream
// gated by the chunk's zero-done event}; join 2nd stream back before return.
// Falls back to single-stream sequential if stream/event creation fails.
// ---------------------------------------------------------------------------
extern "C" void kernel_launch(void* const* d_in, const int* in_sizes, int n_in,
                              void* d_out, int out_size)
{
    const float* edge_features = (const float*)d_in[0];
    const void*  pair_indices  = d_in[1];

    int n_edges = in_sizes[0] / F_DIM;               // robust to index dtype
    int B = out_size / (N_ATOMS * N_ATOMS * F_DIM);  // 32
    int M = n_edges / B;                             // 4096

    float* out = (float*)d_out;

    // One-time resources (created on the first, uncaptured, correctness call).
    static cudaStream_t s2 = nullptr;
    static cudaEvent_t  ev_zero[MAX_CHUNKS];
    static cudaEvent_t  ev_join = nullptr;
    static int          mode = -1;  // -1 uninit, 1 two-stream, 0 fallback
    if (mode < 0) {
        bool ok = (cudaStreamCreateWithFlags(&s2, cudaStreamNonBlocking) == cudaSuccess);
        for (int c = 0; c < MAX_CHUNKS && ok; c++)
            ok = (cudaEventCreateWithFlags(&ev_zero[c], cudaEventDisableTiming) == cudaSuccess);
        if (ok) ok = (cudaEventCreateWithFlags(&ev_join, cudaEventDisableTiming) == cudaSuccess);
        mode = ok ? 1 : 0;
    }

    // K0: pack keys (default stream; chunk-0 zero event also orders it for s2).
    {
        int threads = 256;
        int blocks  = (n_edges + threads - 1) / threads;
        pack_kernel<<<blocks, threads>>>(pair_indices, n_edges);
    }

    int n_chunks = (B + BATCHES_PER_CHUNK - 1) / BATCHES_PER_CHUNK;
    if (n_chunks > MAX_CHUNKS) n_chunks = MAX_CHUNKS;  // (not hit for B=32)

    const int batch_elems = N_ATOMS * N_ATOMS * F_DIM;       // 1,048,576 floats

    for (int c = 0; c < n_chunks; c++) {
        int b0  = c * BATCHES_PER_CHUNK;
        int nb  = (b0 + BATCHES_PER_CHUNK <= B) ? BATCHES_PER_CHUNK : (B - b0);
        int n4  = nb * batch_elems / 4;                      // float4 count
        float* chunk_out = out + (long long)b0 * batch_elems;

        // zero this chunk on the default (capture) stream
        zero_kernel<<<2048, 256>>>((float4*)chunk_out, n4);

        if (mode == 1) {
            cudaEventRecord(ev_zero[c], 0);
            cudaStreamWaitEvent(s2, ev_zero[c], 0);
        }

        // scatter this chunk's edges
        int n_chunk_edges = nb * M;
        int total   = n_chunk_edges * (F_DIM / 4);
        int threads = 256;
        int blocks  = (total + threads - 1) / threads;
        if (mode == 1) {
            scatter_kernel<<<blocks, threads, 0, s2>>>(
                (const float4*)edge_features, out, b0, n_chunk_edges, M);
        } else {
            scatter_kernel<<<blocks, threads>>>(
                (const float4*)edge_features, out, b0, n_chunk_edges, M);
        }
    }

    // Join s2 back into the default stream so the graph's output dependency
    // covers all scatters.
    if (mode == 1) {
        cudaEventRecord(ev_join, s2);
        cudaStreamWaitEvent(0, ev_join, 0);
    }
}

// round 7
// speedup vs baseline: 4.1200x; 1.0025x over previous
#include <cuda_runtime.h>
#include <cstdint>

// Scatter-add edge_features [B, M, F] into out [B, N, N, F] at (b, i, j).
// Sequential chunked zero+scatter: each 33.5 MB output chunk is zeroed
// (write-allocates into L2) and immediately scattered into while L2-resident,
// so atomic RMW never fetches from DRAM; the 134 MB of final writebacks drain
// lazily under later chunks. Dataset: B=32, M=4096, F=64, N=128.

static constexpr int N_ATOMS = 128;
static constexpr int F_DIM   = 64;
static constexpr int MAX_EDGES = 1 << 17;     // B*M
static constexpr int BATCHES_PER_CHUNK = 8;   // 33.5 MB output per chunk

// Packed keys: (i << 8) | j per edge; 0xFFFF = out-of-range sentinel.
__device__ unsigned short g_keys[MAX_EDGES];

// ---------------------------------------------------------------------------
// K0: pack indices into u16 keys; per-block dtype probe (int64 layout => odd
// 32-bit words are zero high halves of values < 128; int32 => random j).
// ---------------------------------------------------------------------------
__global__ void pack_kernel(const void* __restrict__ pair_raw, int n_edges) {
    __shared__ int s_is64;
    const int* words = (const int*)pair_raw;
    if (threadIdx.x < 32) {
        int w = words[threadIdx.x * 2 + 1];
        unsigned ball = __ballot_sync(0xffffffffu, w == 0);
        if (threadIdx.x == 0) s_is64 = (ball == 0xffffffffu) ? 1 : 0;
    }
    __syncthreads();
    const int is64 = s_is64;

    int e = blockIdx.x * blockDim.x + threadIdx.x;
    if (e >= n_edges) return;

    unsigned i, j;
    if (is64) {
        longlong2 v = ((const longlong2*)pair_raw)[e];
        i = (unsigned)v.x; j = (unsigned)v.y;
    } else {
        int2 v = ((const int2*)pair_raw)[e];
        i = (unsigned)v.x; j = (unsigned)v.y;
    }
    g_keys[e] = (i < N_ATOMS && j < N_ATOMS)
                    ? (unsigned short)((i << 8) | j)
                    : (unsigned short)0xFFFF;
}

// ---------------------------------------------------------------------------
// Zero one chunk (default STG -> write-allocates in L2).
// ---------------------------------------------------------------------------
__global__ void zero_kernel(float4* __restrict__ out, int n4) {
    int idx    = blockIdx.x * blockDim.x + threadIdx.x;
    int stride = gridDim.x * blockDim.x;
    float4 z = make_float4(0.f, 0.f, 0.f, 0.f);
    for (; idx < n4; idx += stride) out[idx] = z;
}

// ---------------------------------------------------------------------------
// Scatter one chunk's edges: 16 threads/edge, red.global.add.v4.f32 into the
// freshly zeroed, L2-resident chunk. Edge reads use .cs (evict-first) so the
// streaming input doesn't displace output lines from L2.
// ---------------------------------------------------------------------------
__global__ void scatter_kernel(const float4* __restrict__ edge_feat4,  // base
                               float* __restrict__ out,                // base
                               int b0, int n_chunk_edges, int M)
{
    int tid = blockIdx.x * blockDim.x + threadIdx.x;
    if (tid >= n_chunk_edges * (F_DIM / 4)) return;

    int le    = tid >> 4;
    int chunk = tid & 15;
    int ge    = b0 * M + le;
    int b     = b0 + le / M;

    unsigned short key = g_keys[ge];
    if (key == 0xFFFFu) return;
    unsigned i = key >> 8;
    unsigned j = key & 0xFFu;

    float4 v = __ldcs(&edge_feat4[((long long)ge << 4) + chunk]);

    unsigned dst = ((((unsigned)b * N_ATOMS + i) * N_ATOMS + j) * F_DIM)
                   + (unsigned)chunk * 4;
    float* dptr = out + dst;

    asm volatile("red.global.add.v4.f32 [%0], {%1, %2, %3, %4};"
                 :
                 : "l"(dptr), "f"(v.x), "f"(v.y), "f"(v.z), "f"(v.w)
                 : "memory");
}

// ---------------------------------------------------------------------------
// Launch: pack, then per chunk {zero; scatter} on one stream.
// ---------------------------------------------------------------------------
extern "C" void kernel_launch(void* const* d_in, const int* in_sizes, int n_in,
                              void* d_out, int out_size)
{
    const float* edge_features = (const float*)d_in[0];
    const void*  pair_indices  = d_in[1];

    int n_edges = in_sizes[0] / F_DIM;               // robust to index dtype
    int B = out_size / (N_ATOMS * N_ATOMS * F_DIM);  // 32
    int M = n_edges / B;                             // 4096

    float* out = (float*)d_out;

    // K0: pack keys
    {
        int threads = 256;
        int blocks  = (n_edges + threads - 1) / threads;
        pack_kernel<<<blocks, threads>>>(pair_indices, n_edges);
    }

    const int batch_elems = N_ATOMS * N_ATOMS * F_DIM;   // 1,048,576 floats
    int n_chunks = (B + BATCHES_PER_CHUNK - 1) / BATCHES_PER_CHUNK;

    for (int c = 0; c < n_chunks; c++) {
        int b0 = c * BATCHES_PER_CHUNK;
        int nb = (b0 + BATCHES_PER_CHUNK <= B) ? BATCHES_PER_CHUNK : (B - b0);

        // zero this chunk
        int n4 = nb * batch_elems / 4;
        float* chunk_out = out + (long long)b0 * batch_elems;
        zero_kernel<<<2048, 256>>>((float4*)chunk_out, n4);

        // scatter this chunk's edges
        int n_chunk_edges = nb * M;
        int total   = n_chunk_edges * (F_DIM / 4);
        int threads = 256;
        int blocks  = (total + threads - 1) / threads;
        scatter_kernel<<<blocks, threads>>>((const float4*)edge_features,
                                            out, b0, n_chunk_edges, M);
    }
}

// round 8
// speedup vs baseline: 4.2889x; 1.0410x over previous
#include <cuda_runtime.h>
#include <cstdint>

// Scatter-add edge_features [B, M, F] into out [B, N, N, F] at (b, i, j),
// inverted into a gather: bin edges by destination slot (CSR-with-capacity),
// then emit every output slot exactly once with register accumulation.
// Output is written once (no zero pass, no RMW). B=32, M=4096, F=64, N=128.

static constexpr int N_ATOMS = 128;
static constexpr int F_DIM   = 64;
static constexpr int MAX_B   = 32;
static constexpr int SLOTS   = MAX_B * N_ATOMS * N_ATOMS;  // 524288
static constexpr int CAP     = 16;  // Poisson(0.25): P(>16) ~ 1e-25/slot

__device__ unsigned g_count[SLOTS];           // 2 MB
__device__ unsigned g_entries[SLOTS * CAP];   // 32 MB

// ---------------------------------------------------------------------------
// K0: zero the per-slot counters.
// ---------------------------------------------------------------------------
__global__ void zero_counts_kernel(int n_slots4) {
    int idx    = blockIdx.x * blockDim.x + threadIdx.x;
    int stride = gridDim.x * blockDim.x;
    uint4* c4 = (uint4*)g_count;
    uint4 z = make_uint4(0, 0, 0, 0);
    for (; idx < n_slots4; idx += stride) c4[idx] = z;
}

// ---------------------------------------------------------------------------
// K1: bin edges into slots. Per-block dtype probe (int64 layout => odd 32-bit
// words are zero high halves of values < 128; int32 => random j in [0,128)).
// ---------------------------------------------------------------------------
__global__ void bin_kernel(const void* __restrict__ pair_raw,
                           int n_edges, int M) {
    __shared__ int s_is64;
    const int* words = (const int*)pair_raw;
    if (threadIdx.x < 32) {
        int w = words[threadIdx.x * 2 + 1];
        unsigned ball = __ballot_sync(0xffffffffu, w == 0);
        if (threadIdx.x == 0) s_is64 = (ball == 0xffffffffu) ? 1 : 0;
    }
    __syncthreads();
    const int is64 = s_is64;

    int e = blockIdx.x * blockDim.x + threadIdx.x;
    if (e >= n_edges) return;

    unsigned i, j;
    if (is64) {
        longlong2 v = ((const longlong2*)pair_raw)[e];
        i = (unsigned)v.x; j = (unsigned)v.y;
    } else {
        int2 v = ((const int2*)pair_raw)[e];
        i = (unsigned)v.x; j = (unsigned)v.y;
    }
    if (i >= N_ATOMS || j >= N_ATOMS) return;  // skip invalid

    int b = e / M;
    unsigned slot = ((unsigned)b * N_ATOMS + i) * N_ATOMS + j;
    unsigned pos  = atomicAdd(&g_count[slot], 1u);
    if (pos < CAP) g_entries[slot * CAP + pos] = (unsigned)e;
}

// ---------------------------------------------------------------------------
// K2: emit. 16 threads per slot, one float4 of F=64 each. Register
// accumulation over the slot's edge list; single STG per float4.
// ---------------------------------------------------------------------------
__global__ void __launch_bounds__(256)
emit_kernel(const float4* __restrict__ edge_feat4,  // [B*M*16]
            float* __restrict__ out,                // [B*N*N*F]
            int n_slots)
{
    int tid = blockIdx.x * blockDim.x + threadIdx.x;
    if (tid >= n_slots * 16) return;

    int slot  = tid >> 4;
    int chunk = tid & 15;

    unsigned cnt = __ldg(&g_count[slot]);
    if (cnt > CAP) cnt = CAP;

    float4 acc = make_float4(0.f, 0.f, 0.f, 0.f);
    const unsigned* ent = &g_entries[slot * CAP];
    for (unsigned k = 0; k < cnt; k++) {
        unsigned e = __ldg(&ent[k]);
        float4 v = __ldcs(&edge_feat4[((long long)e << 4) + chunk]);
        acc.x += v.x; acc.y += v.y; acc.z += v.z; acc.w += v.w;
    }

    // store the finished float4 exactly once (streaming store)
    float4* dst = (float4*)(out) + (long long)slot * 16 + chunk;
    __stcs(dst, acc);
}

// ---------------------------------------------------------------------------
// Launch
// ---------------------------------------------------------------------------
extern "C" void kernel_launch(void* const* d_in, const int* in_sizes, int n_in,
                              void* d_out, int out_size)
{
    const float* edge_features = (const float*)d_in[0];
    const void*  pair_indices  = d_in[1];

    int n_edges = in_sizes[0] / F_DIM;               // robust to index dtype
    int B = out_size / (N_ATOMS * N_ATOMS * F_DIM);  // 32
    int M = n_edges / B;                             // 4096
    int n_slots = B * N_ATOMS * N_ATOMS;             // 524288

    float* out = (float*)d_out;

    // K0: zero counters (uint4-vectorized)
    zero_counts_kernel<<<512, 256>>>(n_slots / 4);

    // K1: bin edges
    {
        int threads = 256;
        int blocks  = (n_edges + threads - 1) / threads;
        bin_kernel<<<blocks, threads>>>(pair_indices, n_edges, M);
    }

    // K2: emit output, one write per element
    {
        int total   = n_slots * 16;                  // 8,388,608 threads
        int threads = 256;
        int blocks  = (total + threads - 1) / threads;
        emit_kernel<<<blocks, threads>>>((const float4*)edge_features,
                                         out, n_slots);
    }
}